// round 2
// baseline (speedup 1.0000x reference)
#include <cuda_runtime.h>
#include <cuda_bf16.h>
#include <math.h>

// Problem constants
#define BZ 2
#define TT 2048
#define EE 4096
#define HQ 32
#define HKV 8
#define DD 128
#define GG 4
#define MM (BZ * TT)          // 4096 rows
#define KVE (HKV * DD)        // 1024

// ---------------- scratch (no cudaMalloc allowed) ----------------
__device__ float g_Q[(size_t)MM * EE];    // 64 MB  (B,T,HQ,D)
__device__ float g_K[(size_t)MM * KVE];   // 16 MB  (B,T,HKV,D)
__device__ float g_V[(size_t)MM * KVE];   // 16 MB
__device__ float g_Y[(size_t)MM * EE];    // 64 MB  attention output (B,T,HQ,D)

// ---------------- GEMM: C[m,n] = sum_k A[m,k]*B[n,k] + bias[n] ----------------
// A: (M,K) row-major, B: (N,K) row-major (NT gemm, both K-contiguous)
#define BM 128
#define BN 128
#define BK 16
__global__ __launch_bounds__(256) void gemm_nt_kernel(
    const float* __restrict__ A, const float* __restrict__ Bm,
    const float* __restrict__ bias, float* __restrict__ C,
    int M, int N, int K)
{
    __shared__ float As[BK][BM + 4];
    __shared__ float Bs[BK][BN + 4];

    const int tid = threadIdx.x;
    const int bm = blockIdx.y * BM;
    const int bn = blockIdx.x * BN;

    const int lrow = tid >> 1;          // 0..127
    const int lcol = (tid & 1) * 8;     // 0 or 8
    const int tx = tid & 15;            // 0..15
    const int ty = tid >> 4;            // 0..15

    float acc[8][8];
#pragma unroll
    for (int i = 0; i < 8; i++)
#pragma unroll
        for (int j = 0; j < 8; j++) acc[i][j] = 0.f;

    const float* Aptr = A + (size_t)(bm + lrow) * K + lcol;
    const float* Bptr = Bm + (size_t)(bn + lrow) * K + lcol;

    for (int k0 = 0; k0 < K; k0 += BK) {
        float4 a0 = *(const float4*)(Aptr + k0);
        float4 a1 = *(const float4*)(Aptr + k0 + 4);
        float4 b0 = *(const float4*)(Bptr + k0);
        float4 b1 = *(const float4*)(Bptr + k0 + 4);
        As[lcol + 0][lrow] = a0.x; As[lcol + 1][lrow] = a0.y;
        As[lcol + 2][lrow] = a0.z; As[lcol + 3][lrow] = a0.w;
        As[lcol + 4][lrow] = a1.x; As[lcol + 5][lrow] = a1.y;
        As[lcol + 6][lrow] = a1.z; As[lcol + 7][lrow] = a1.w;
        Bs[lcol + 0][lrow] = b0.x; Bs[lcol + 1][lrow] = b0.y;
        Bs[lcol + 2][lrow] = b0.z; Bs[lcol + 3][lrow] = b0.w;
        Bs[lcol + 4][lrow] = b1.x; Bs[lcol + 5][lrow] = b1.y;
        Bs[lcol + 6][lrow] = b1.z; Bs[lcol + 7][lrow] = b1.w;
        __syncthreads();

#pragma unroll
        for (int kk = 0; kk < BK; kk++) {
            float ar[8], br[8];
            float4 t0 = *(const float4*)(&As[kk][ty * 8]);
            float4 t1 = *(const float4*)(&As[kk][ty * 8 + 4]);
            ar[0]=t0.x; ar[1]=t0.y; ar[2]=t0.z; ar[3]=t0.w;
            ar[4]=t1.x; ar[5]=t1.y; ar[6]=t1.z; ar[7]=t1.w;
            float4 u0 = *(const float4*)(&Bs[kk][tx * 8]);
            float4 u1 = *(const float4*)(&Bs[kk][tx * 8 + 4]);
            br[0]=u0.x; br[1]=u0.y; br[2]=u0.z; br[3]=u0.w;
            br[4]=u1.x; br[5]=u1.y; br[6]=u1.z; br[7]=u1.w;
#pragma unroll
            for (int i = 0; i < 8; i++)
#pragma unroll
                for (int j = 0; j < 8; j++)
                    acc[i][j] = fmaf(ar[i], br[j], acc[i][j]);
        }
        __syncthreads();
    }

    // epilogue with bias
#pragma unroll
    for (int i = 0; i < 8; i++) {
        int m = bm + ty * 8 + i;
        float* crow = C + (size_t)m * N + bn + tx * 8;
        const float* bp = bias + bn + tx * 8;
        float4 o0, o1;
        o0.x = acc[i][0] + bp[0]; o0.y = acc[i][1] + bp[1];
        o0.z = acc[i][2] + bp[2]; o0.w = acc[i][3] + bp[3];
        o1.x = acc[i][4] + bp[4]; o1.y = acc[i][5] + bp[5];
        o1.z = acc[i][6] + bp[6]; o1.w = acc[i][7] + bp[7];
        *(float4*)(crow) = o0;
        *(float4*)(crow + 4) = o1;
    }
}

// ---------------- RoPE (in-place) ----------------
// X: (B, T, H, D) row-major; fr: (T, D/2, 2)
__global__ void rope_kernel(float* __restrict__ X, const float* __restrict__ fr, int H)
{
    int idx = blockIdx.x * blockDim.x + threadIdx.x;
    int total = BZ * TT * H * (DD / 2);
    if (idx >= total) return;
    int j = idx % (DD / 2);
    int h = (idx / (DD / 2)) % H;
    int t = (idx / ((DD / 2) * H)) % TT;
    int b = idx / ((DD / 2) * H * TT);
    float c = fr[(t * (DD / 2) + j) * 2 + 0];
    float s = fr[(t * (DD / 2) + j) * 2 + 1];
    size_t base = (((size_t)b * TT + t) * H + h) * DD + 2 * j;
    float x0 = X[base], x1 = X[base + 1];
    X[base]     = x0 * c - x1 * s;
    X[base + 1] = x1 * c + x0 * s;
}

// ---------------- Flash attention (causal, GQA) ----------------
#define BQ 64
#define BKT 64
#define QSTRIDE 132   // 128 + 4 pad, keeps float4 alignment (132*4=528 bytes, /16 ok)
#define SSTRIDE 68

// smem layout (floats):
//  Qs [BQ*QSTRIDE] | Ks [BKT*QSTRIDE] | Vs [BKT*QSTRIDE] | Ss [BQ*SSTRIDE] | fac[BQ] | mrow[BQ] | lrow[BQ]
#define FLASH_SMEM_FLOATS (BQ*QSTRIDE + BKT*QSTRIDE + BKT*QSTRIDE + BQ*SSTRIDE + 3*BQ)
#define FLASH_SMEM_BYTES (FLASH_SMEM_FLOATS * 4)

__global__ __launch_bounds__(256) void flash_attn_kernel(
    const float* __restrict__ Q, const float* __restrict__ K,
    const float* __restrict__ V, float* __restrict__ Y)
{
    extern __shared__ float sm[];
    float* Qs = sm;
    float* Ks = Qs + BQ * QSTRIDE;
    float* Vs = Ks + BKT * QSTRIDE;
    float* Ss = Vs + BKT * QSTRIDE;
    float* fac  = Ss + BQ * SSTRIDE;
    float* mrow = fac + BQ;
    float* lrow = mrow + BQ;

    const int tid = threadIdx.x;
    const int tx = tid & 15;      // 0..15
    const int ty = tid >> 4;      // 0..15
    const int q0 = blockIdx.x * BQ;
    const int h  = blockIdx.y;
    const int b  = blockIdx.z;
    const int hk = h / GG;
    const float scale = rsqrtf((float)DD);

    // load Q tile: (b, q0+r, h, :) -> Qs[r][:]
    for (int i = tid; i < BQ * (DD / 4); i += 256) {
        int r = i >> 5;          // /32
        int c4 = (i & 31) * 4;
        float4 v = *(const float4*)(Q + ((((size_t)b * TT + q0 + r) * HQ + h) * DD + c4));
        *(float4*)(Qs + r * QSTRIDE + c4) = v;
    }
    if (tid < BQ) { mrow[tid] = -1e30f; lrow[tid] = 0.f; }

    float o[4][8];
#pragma unroll
    for (int i = 0; i < 4; i++)
#pragma unroll
        for (int j = 0; j < 8; j++) o[i][j] = 0.f;

    const int ktiles = q0 / BKT + 1;
    for (int kt = 0; kt < ktiles; kt++) {
        const int k0 = kt * BKT;
        // load K,V tiles
        for (int i = tid; i < BKT * (DD / 4); i += 256) {
            int r = i >> 5;
            int c4 = (i & 31) * 4;
            size_t gidx = (((size_t)b * TT + k0 + r) * HKV + hk) * DD + c4;
            *(float4*)(Ks + r * QSTRIDE + c4) = *(const float4*)(K + gidx);
            *(float4*)(Vs + r * QSTRIDE + c4) = *(const float4*)(V + gidx);
        }
        __syncthreads();

        // S = Q K^T : thread computes S[ty*4+i][tx*4+j]
        float s[4][4];
#pragma unroll
        for (int i = 0; i < 4; i++)
#pragma unroll
            for (int j = 0; j < 4; j++) s[i][j] = 0.f;

        for (int d4 = 0; d4 < DD; d4 += 4) {
            float4 qv[4], kv[4];
#pragma unroll
            for (int i = 0; i < 4; i++) qv[i] = *(const float4*)(Qs + (ty * 4 + i) * QSTRIDE + d4);
#pragma unroll
            for (int j = 0; j < 4; j++) kv[j] = *(const float4*)(Ks + (tx * 4 + j) * QSTRIDE + d4);
#pragma unroll
            for (int i = 0; i < 4; i++)
#pragma unroll
                for (int j = 0; j < 4; j++) {
                    s[i][j] = fmaf(qv[i].x, kv[j].x, s[i][j]);
                    s[i][j] = fmaf(qv[i].y, kv[j].y, s[i][j]);
                    s[i][j] = fmaf(qv[i].z, kv[j].z, s[i][j]);
                    s[i][j] = fmaf(qv[i].w, kv[j].w, s[i][j]);
                }
        }
        // scale + causal mask + stash
#pragma unroll
        for (int i = 0; i < 4; i++)
#pragma unroll
            for (int j = 0; j < 4; j++) {
                float val = s[i][j] * scale;
                if (k0 + tx * 4 + j > q0 + ty * 4 + i) val = -1e30f;
                Ss[(ty * 4 + i) * SSTRIDE + tx * 4 + j] = val;
            }
        __syncthreads();

        // online softmax, one thread per row
        if (tid < BQ) {
            int r = tid;
            float mo = mrow[r];
            float mx = mo;
            for (int c = 0; c < BKT; c++) mx = fmaxf(mx, Ss[r * SSTRIDE + c]);
            float sum = 0.f;
            for (int c = 0; c < BKT; c++) {
                float p = __expf(Ss[r * SSTRIDE + c] - mx);
                Ss[r * SSTRIDE + c] = p;
                sum += p;
            }
            float f = __expf(mo - mx);
            lrow[r] = lrow[r] * f + sum;
            mrow[r] = mx;
            fac[r] = f;
        }
        __syncthreads();

        // O = O*fac + P@V : thread rows ty*4+i, cols tx*8..tx*8+7
#pragma unroll
        for (int i = 0; i < 4; i++) {
            float f = fac[ty * 4 + i];
#pragma unroll
            for (int j = 0; j < 8; j++) o[i][j] *= f;
        }
        for (int k = 0; k < BKT; k++) {
            float4 v0 = *(const float4*)(Vs + k * QSTRIDE + tx * 8);
            float4 v1 = *(const float4*)(Vs + k * QSTRIDE + tx * 8 + 4);
#pragma unroll
            for (int i = 0; i < 4; i++) {
                float p = Ss[(ty * 4 + i) * SSTRIDE + k];
                o[i][0] = fmaf(p, v0.x, o[i][0]);
                o[i][1] = fmaf(p, v0.y, o[i][1]);
                o[i][2] = fmaf(p, v0.z, o[i][2]);
                o[i][3] = fmaf(p, v0.w, o[i][3]);
                o[i][4] = fmaf(p, v1.x, o[i][4]);
                o[i][5] = fmaf(p, v1.y, o[i][5]);
                o[i][6] = fmaf(p, v1.z, o[i][6]);
                o[i][7] = fmaf(p, v1.w, o[i][7]);
            }
        }
        __syncthreads();
    }

    // epilogue: divide by l, write (B,T,HQ,D)
#pragma unroll
    for (int i = 0; i < 4; i++) {
        float inv = 1.f / lrow[ty * 4 + i];
        float* yp = Y + ((((size_t)b * TT + q0 + ty * 4 + i) * HQ + h) * DD + tx * 8);
        float4 o0, o1;
        o0.x = o[i][0] * inv; o0.y = o[i][1] * inv; o0.z = o[i][2] * inv; o0.w = o[i][3] * inv;
        o1.x = o[i][4] * inv; o1.y = o[i][5] * inv; o1.z = o[i][6] * inv; o1.w = o[i][7] * inv;
        *(float4*)(yp) = o0;
        *(float4*)(yp + 4) = o1;
    }
}

// ---------------- launch ----------------
extern "C" void kernel_launch(void* const* d_in, const int* in_sizes, int n_in,
                              void* d_out, int out_size)
{
    const float* query = (const float*)d_in[0];
    const float* key   = (const float*)d_in[1];
    const float* value = (const float*)d_in[2];
    const float* freqs = (const float*)d_in[3];
    // d_in[4] = mask (int32 tril) -- causal logic handled analytically
    const float* Wq = (const float*)d_in[5];
    const float* bq = (const float*)d_in[6];
    const float* Wk = (const float*)d_in[7];
    const float* bk = (const float*)d_in[8];
    const float* Wv = (const float*)d_in[9];
    const float* bv = (const float*)d_in[10];
    const float* Wo = (const float*)d_in[11];
    const float* bo = (const float*)d_in[12];
    float* out = (float*)d_out;

    float *Qb, *Kb, *Vb, *Yb;
    cudaGetSymbolAddress((void**)&Qb, g_Q);
    cudaGetSymbolAddress((void**)&Kb, g_K);
    cudaGetSymbolAddress((void**)&Vb, g_V);
    cudaGetSymbolAddress((void**)&Yb, g_Y);

    cudaFuncSetAttribute(flash_attn_kernel,
                         cudaFuncAttributeMaxDynamicSharedMemorySize, FLASH_SMEM_BYTES);

    dim3 blk(256);
    // projections
    gemm_nt_kernel<<<dim3(EE / BN, MM / BM), blk>>>(query, Wq, bq, Qb, MM, EE, EE);
    gemm_nt_kernel<<<dim3(KVE / BN, MM / BM), blk>>>(key, Wk, bk, Kb, MM, KVE, EE);
    gemm_nt_kernel<<<dim3(KVE / BN, MM / BM), blk>>>(value, Wv, bv, Vb, MM, KVE, EE);

    // RoPE
    {
        int totq = BZ * TT * HQ * (DD / 2);
        rope_kernel<<<(totq + 255) / 256, 256>>>(Qb, freqs, HQ);
        int totk = BZ * TT * HKV * (DD / 2);
        rope_kernel<<<(totk + 255) / 256, 256>>>(Kb, freqs, HKV);
    }

    // attention
    flash_attn_kernel<<<dim3(TT / BQ, HQ, BZ), 256, FLASH_SMEM_BYTES>>>(Qb, Kb, Vb, Yb);

    // output projection -> d_out
    gemm_nt_kernel<<<dim3(EE / BN, MM / BM), blk>>>(Yb, Wo, bo, out, MM, EE, EE);
}

// round 9
// speedup vs baseline: 1.5308x; 1.5308x over previous
#include <cuda_runtime.h>
#include <cuda_bf16.h>
#include <math.h>
#include <cstdint>

// Problem constants
#define BZ 2
#define TT 2048
#define EE 4096
#define HQ 32
#define HKV 8
#define DD 128
#define GG 4
#define MM (BZ * TT)          // 4096 rows
#define KVE (HKV * DD)        // 1024

// ---------------- scratch (no cudaMalloc allowed) ----------------
__device__ float g_Q[(size_t)MM * EE];    // 64 MB  (B,T,HQ,D)
__device__ float g_K[(size_t)MM * KVE];   // 16 MB  (B,T,HKV,D)
__device__ float g_V[(size_t)MM * KVE];   // 16 MB
__device__ float g_Y[(size_t)MM * EE];    // 64 MB  attention output (B,T,HQ,D)

__device__ __forceinline__ uint32_t f2tf32(float f) {
    uint32_t r;
    asm("cvt.rna.tf32.f32 %0, %1;" : "=r"(r) : "f"(f));
    return r;
}

// tf32 warp MMA: D(16x8) += A(16x8) * B(8x8); A row-major frag, B col-major frag
__device__ __forceinline__ void mma_tf32(float* c,
                                         uint32_t a0, uint32_t a1, uint32_t a2, uint32_t a3,
                                         uint32_t b0, uint32_t b1) {
    asm volatile(
        "mma.sync.aligned.m16n8k8.row.col.f32.tf32.tf32.f32 "
        "{%0,%1,%2,%3}, {%4,%5,%6,%7}, {%8,%9}, {%0,%1,%2,%3};"
        : "+f"(c[0]), "+f"(c[1]), "+f"(c[2]), "+f"(c[3])
        : "r"(a0), "r"(a1), "r"(a2), "r"(a3), "r"(b0), "r"(b1));
}

// =================== tf32 mma.sync GEMM ===================
// C[m,n] = sum_k A[m,k]*B[n,k] + bias[n]; A (M,K), B (N,K) row-major fp32
// Block: 128x128x16, 8 warps, warp tile 64x32 (4x4 m16n8k8 frags)
#define BM 128
#define BN 128
#define BK 16
#define ASTRIDE (BM + 4)
#define BSTRIDE (BN + 4)

__global__ __launch_bounds__(256) void gemm_mma_kernel(
    const float* __restrict__ A, const float* __restrict__ Bm,
    const float* __restrict__ bias, float* __restrict__ C,
    int M, int N, int K)
{
    __shared__ uint32_t As[BK][ASTRIDE];   // tf32 bits, k-major
    __shared__ uint32_t Bs[BK][BSTRIDE];

    const int tid = threadIdx.x;
    const int wid = tid >> 5;
    const int lane = tid & 31;
    const int bm = blockIdx.y * BM;
    const int bn = blockIdx.x * BN;

    const int warp_m = (wid >> 2) * 64;    // 0 or 64
    const int warp_n = (wid & 3) * 32;     // 0,32,64,96

    float acc[4][4][4];
#pragma unroll
    for (int i = 0; i < 4; i++)
#pragma unroll
        for (int j = 0; j < 4; j++)
#pragma unroll
            for (int r = 0; r < 4; r++) acc[i][j][r] = 0.f;

    // global load mapping: row = tid>>1 (0..127), lcol = (tid&1)*8
    const int grow = tid >> 1;
    const int lcol = (tid & 1) * 8;
    const float* Aptr = A + (size_t)(bm + grow) * K + lcol;
    const float* Bptr = Bm + (size_t)(bn + grow) * K + lcol;

    const int lq = lane >> 2;   // 0..7
    const int lr = lane & 3;    // 0..3

    for (int k0 = 0; k0 < K; k0 += BK) {
        float4 a0 = *(const float4*)(Aptr + k0);
        float4 a1 = *(const float4*)(Aptr + k0 + 4);
        float4 b0 = *(const float4*)(Bptr + k0);
        float4 b1 = *(const float4*)(Bptr + k0 + 4);
        As[lcol + 0][grow] = f2tf32(a0.x); As[lcol + 1][grow] = f2tf32(a0.y);
        As[lcol + 2][grow] = f2tf32(a0.z); As[lcol + 3][grow] = f2tf32(a0.w);
        As[lcol + 4][grow] = f2tf32(a1.x); As[lcol + 5][grow] = f2tf32(a1.y);
        As[lcol + 6][grow] = f2tf32(a1.z); As[lcol + 7][grow] = f2tf32(a1.w);
        Bs[lcol + 0][grow] = f2tf32(b0.x); Bs[lcol + 1][grow] = f2tf32(b0.y);
        Bs[lcol + 2][grow] = f2tf32(b0.z); Bs[lcol + 3][grow] = f2tf32(b0.w);
        Bs[lcol + 4][grow] = f2tf32(b1.x); Bs[lcol + 5][grow] = f2tf32(b1.y);
        Bs[lcol + 6][grow] = f2tf32(b1.z); Bs[lcol + 7][grow] = f2tf32(b1.w);
        __syncthreads();

#pragma unroll
        for (int ks = 0; ks < BK; ks += 8) {
            // A fragments: a0=(r,c) a1=(r+8,c) a2=(r,c+4) a3=(r+8,c+4)
            uint32_t af[4][4];
#pragma unroll
            for (int mt = 0; mt < 4; mt++) {
                int r = warp_m + mt * 16 + lq;
                int c = ks + lr;
                af[mt][0] = As[c][r];
                af[mt][1] = As[c][r + 8];
                af[mt][2] = As[c + 4][r];
                af[mt][3] = As[c + 4][r + 8];
            }
            // B fragments (col-major k8n8): b0=(k,n) b1=(k+4,n), n = lane>>2, k = lane&3
            uint32_t bf[4][2];
#pragma unroll
            for (int nt = 0; nt < 4; nt++) {
                int n = warp_n + nt * 8 + lq;
                int k = ks + lr;
                bf[nt][0] = Bs[k][n];
                bf[nt][1] = Bs[k + 4][n];
            }
#pragma unroll
            for (int mt = 0; mt < 4; mt++)
#pragma unroll
                for (int nt = 0; nt < 4; nt++)
                    mma_tf32(acc[mt][nt], af[mt][0], af[mt][1], af[mt][2], af[mt][3],
                             bf[nt][0], bf[nt][1]);
        }
        __syncthreads();
    }

    // epilogue: frag layout c0=(r, 2c) c1=(r, 2c+1) c2=(r+8, 2c) c3=(r+8, 2c+1)
#pragma unroll
    for (int mt = 0; mt < 4; mt++) {
#pragma unroll
        for (int nt = 0; nt < 4; nt++) {
            int r0 = bm + warp_m + mt * 16 + lq;
            int c0 = bn + warp_n + nt * 8 + lr * 2;
            float bvx = bias[c0], bvy = bias[c0 + 1];
            float2 v0 = make_float2(acc[mt][nt][0] + bvx, acc[mt][nt][1] + bvy);
            float2 v1 = make_float2(acc[mt][nt][2] + bvx, acc[mt][nt][3] + bvy);
            *(float2*)(C + (size_t)r0 * N + c0) = v0;
            *(float2*)(C + (size_t)(r0 + 8) * N + c0) = v1;
        }
    }
}

// ---------------- RoPE (in-place) ----------------
__global__ void rope_kernel(float* __restrict__ X, const float* __restrict__ fr, int H)
{
    int idx = blockIdx.x * blockDim.x + threadIdx.x;
    int total = BZ * TT * H * (DD / 2);
    if (idx >= total) return;
    int j = idx % (DD / 2);
    int h = (idx / (DD / 2)) % H;
    int t = (idx / ((DD / 2) * H)) % TT;
    int b = idx / ((DD / 2) * H * TT);
    float c = fr[(t * (DD / 2) + j) * 2 + 0];
    float s = fr[(t * (DD / 2) + j) * 2 + 1];
    size_t base = (((size_t)b * TT + t) * H + h) * DD + 2 * j;
    float x0 = X[base], x1 = X[base + 1];
    X[base]     = x0 * c - x1 * s;
    X[base + 1] = x1 * c + x0 * s;
}

// ---------------- Flash attention (causal, GQA, fp32) ----------------
#define BQ 64
#define BKT 64
#define QSTRIDE 132
#define SSTRIDE 68
#define FLASH_SMEM_FLOATS (BQ*QSTRIDE + BKT*QSTRIDE + BKT*QSTRIDE + BQ*SSTRIDE + 3*BQ)
#define FLASH_SMEM_BYTES (FLASH_SMEM_FLOATS * 4)

__global__ __launch_bounds__(256) void flash_attn_kernel(
    const float* __restrict__ Q, const float* __restrict__ K,
    const float* __restrict__ V, float* __restrict__ Y)
{
    extern __shared__ float sm[];
    float* Qs = sm;
    float* Ks = Qs + BQ * QSTRIDE;
    float* Vs = Ks + BKT * QSTRIDE;
    float* Ss = Vs + BKT * QSTRIDE;
    float* fac  = Ss + BQ * SSTRIDE;
    float* mrow = fac + BQ;
    float* lrow = mrow + BQ;

    const int tid = threadIdx.x;
    const int tx = tid & 15;
    const int ty = tid >> 4;
    const int q0 = blockIdx.x * BQ;
    const int h  = blockIdx.y;
    const int b  = blockIdx.z;
    const int hk = h / GG;
    const float scale = rsqrtf((float)DD);

    for (int i = tid; i < BQ * (DD / 4); i += 256) {
        int r = i >> 5;
        int c4 = (i & 31) * 4;
        float4 v = *(const float4*)(Q + ((((size_t)b * TT + q0 + r) * HQ + h) * DD + c4));
        *(float4*)(Qs + r * QSTRIDE + c4) = v;
    }
    if (tid < BQ) { mrow[tid] = -1e30f; lrow[tid] = 0.f; }

    float o[4][8];
#pragma unroll
    for (int i = 0; i < 4; i++)
#pragma unroll
        for (int j = 0; j < 8; j++) o[i][j] = 0.f;

    const int ktiles = q0 / BKT + 1;
    for (int kt = 0; kt < ktiles; kt++) {
        const int k0 = kt * BKT;
        for (int i = tid; i < BKT * (DD / 4); i += 256) {
            int r = i >> 5;
            int c4 = (i & 31) * 4;
            size_t gidx = (((size_t)b * TT + k0 + r) * HKV + hk) * DD + c4;
            *(float4*)(Ks + r * QSTRIDE + c4) = *(const float4*)(K + gidx);
            *(float4*)(Vs + r * QSTRIDE + c4) = *(const float4*)(V + gidx);
        }
        __syncthreads();

        float s[4][4];
#pragma unroll
        for (int i = 0; i < 4; i++)
#pragma unroll
            for (int j = 0; j < 4; j++) s[i][j] = 0.f;

        for (int d4 = 0; d4 < DD; d4 += 4) {
            float4 qv[4], kv[4];
#pragma unroll
            for (int i = 0; i < 4; i++) qv[i] = *(const float4*)(Qs + (ty * 4 + i) * QSTRIDE + d4);
#pragma unroll
            for (int j = 0; j < 4; j++) kv[j] = *(const float4*)(Ks + (tx * 4 + j) * QSTRIDE + d4);
#pragma unroll
            for (int i = 0; i < 4; i++)
#pragma unroll
                for (int j = 0; j < 4; j++) {
                    s[i][j] = fmaf(qv[i].x, kv[j].x, s[i][j]);
                    s[i][j] = fmaf(qv[i].y, kv[j].y, s[i][j]);
                    s[i][j] = fmaf(qv[i].z, kv[j].z, s[i][j]);
                    s[i][j] = fmaf(qv[i].w, kv[j].w, s[i][j]);
                }
        }
#pragma unroll
        for (int i = 0; i < 4; i++)
#pragma unroll
            for (int j = 0; j < 4; j++) {
                float val = s[i][j] * scale;
                if (k0 + tx * 4 + j > q0 + ty * 4 + i) val = -1e30f;
                Ss[(ty * 4 + i) * SSTRIDE + tx * 4 + j] = val;
            }
        __syncthreads();

        if (tid < BQ) {
            int r = tid;
            float mo = mrow[r];
            float mx = mo;
            for (int c = 0; c < BKT; c++) mx = fmaxf(mx, Ss[r * SSTRIDE + c]);
            float sum = 0.f;
            for (int c = 0; c < BKT; c++) {
                float p = __expf(Ss[r * SSTRIDE + c] - mx);
                Ss[r * SSTRIDE + c] = p;
                sum += p;
            }
            float f = __expf(mo - mx);
            lrow[r] = lrow[r] * f + sum;
            mrow[r] = mx;
            fac[r] = f;
        }
        __syncthreads();

#pragma unroll
        for (int i = 0; i < 4; i++) {
            float f = fac[ty * 4 + i];
#pragma unroll
            for (int j = 0; j < 8; j++) o[i][j] *= f;
        }
        for (int k = 0; k < BKT; k++) {
            float4 v0 = *(const float4*)(Vs + k * QSTRIDE + tx * 8);
            float4 v1 = *(const float4*)(Vs + k * QSTRIDE + tx * 8 + 4);
#pragma unroll
            for (int i = 0; i < 4; i++) {
                float p = Ss[(ty * 4 + i) * SSTRIDE + k];
                o[i][0] = fmaf(p, v0.x, o[i][0]);
                o[i][1] = fmaf(p, v0.y, o[i][1]);
                o[i][2] = fmaf(p, v0.z, o[i][2]);
                o[i][3] = fmaf(p, v0.w, o[i][3]);
                o[i][4] = fmaf(p, v1.x, o[i][4]);
                o[i][5] = fmaf(p, v1.y, o[i][5]);
                o[i][6] = fmaf(p, v1.z, o[i][6]);
                o[i][7] = fmaf(p, v1.w, o[i][7]);
            }
        }
        __syncthreads();
    }

#pragma unroll
    for (int i = 0; i < 4; i++) {
        float inv = 1.f / lrow[ty * 4 + i];
        float* yp = Y + ((((size_t)b * TT + q0 + ty * 4 + i) * HQ + h) * DD + tx * 8);
        float4 o0, o1;
        o0.x = o[i][0] * inv; o0.y = o[i][1] * inv; o0.z = o[i][2] * inv; o0.w = o[i][3] * inv;
        o1.x = o[i][4] * inv; o1.y = o[i][5] * inv; o1.z = o[i][6] * inv; o1.w = o[i][7] * inv;
        *(float4*)(yp) = o0;
        *(float4*)(yp + 4) = o1;
    }
}

// ---------------- launch ----------------
extern "C" void kernel_launch(void* const* d_in, const int* in_sizes, int n_in,
                              void* d_out, int out_size)
{
    const float* query = (const float*)d_in[0];
    const float* key   = (const float*)d_in[1];
    const float* value = (const float*)d_in[2];
    const float* freqs = (const float*)d_in[3];
    const float* Wq = (const float*)d_in[5];
    const float* bq = (const float*)d_in[6];
    const float* Wk = (const float*)d_in[7];
    const float* bk = (const float*)d_in[8];
    const float* Wv = (const float*)d_in[9];
    const float* bv = (const float*)d_in[10];
    const float* Wo = (const float*)d_in[11];
    const float* bo = (const float*)d_in[12];
    float* out = (float*)d_out;

    float *Qb, *Kb, *Vb, *Yb;
    cudaGetSymbolAddress((void**)&Qb, g_Q);
    cudaGetSymbolAddress((void**)&Kb, g_K);
    cudaGetSymbolAddress((void**)&Vb, g_V);
    cudaGetSymbolAddress((void**)&Yb, g_Y);

    cudaFuncSetAttribute(flash_attn_kernel,
                         cudaFuncAttributeMaxDynamicSharedMemorySize, FLASH_SMEM_BYTES);

    dim3 blk(256);
    // projections (tf32 mma.sync tensor cores)
    gemm_mma_kernel<<<dim3(EE / BN, MM / BM), blk>>>(query, Wq, bq, Qb, MM, EE, EE);
    gemm_mma_kernel<<<dim3(KVE / BN, MM / BM), blk>>>(key,   Wk, bk, Kb, MM, KVE, EE);
    gemm_mma_kernel<<<dim3(KVE / BN, MM / BM), blk>>>(value, Wv, bv, Vb, MM, KVE, EE);

    // RoPE
    {
        int totq = BZ * TT * HQ * (DD / 2);
        rope_kernel<<<(totq + 255) / 256, 256>>>(Qb, freqs, HQ);
        int totk = BZ * TT * HKV * (DD / 2);
        rope_kernel<<<(totk + 255) / 256, 256>>>(Kb, freqs, HKV);
    }

    // attention (fp32 flash)
    flash_attn_kernel<<<dim3(TT / BQ, HQ, BZ), 256, FLASH_SMEM_BYTES>>>(Qb, Kb, Vb, Yb);

    // output projection -> d_out (tf32 mma.sync)
    gemm_mma_kernel<<<dim3(EE / BN, MM / BM), blk>>>(Yb, Wo, bo, out, MM, EE, EE);
}

// round 10
// speedup vs baseline: 1.6729x; 1.0928x over previous
#include <cuda_runtime.h>
#include <cuda_bf16.h>
#include <math.h>
#include <cstdint>

// Problem constants
#define BZ 2
#define TT 2048
#define EE 4096
#define HQ 32
#define HKV 8
#define DD 128
#define GG 4
#define MM (BZ * TT)          // 4096 rows
#define KVE (HKV * DD)        // 1024

// ---------------- scratch (no cudaMalloc allowed) ----------------
__device__ float g_Q[(size_t)MM * EE];    // 64 MB  (B,T,HQ,D)
__device__ float g_K[(size_t)MM * KVE];   // 16 MB  (B,T,HKV,D)
__device__ float g_V[(size_t)MM * KVE];   // 16 MB
__device__ float g_Y[(size_t)MM * EE];    // 64 MB  attention output (B,T,HQ,D)

__device__ __forceinline__ uint32_t f2tf32(float f) {
    uint32_t r;
    asm("cvt.rna.tf32.f32 %0, %1;" : "=r"(r) : "f"(f));
    return r;
}

// tf32 warp MMA: D(16x8) += A(16x8) * B(8x8); A row-major frag, B col-major frag
__device__ __forceinline__ void mma_tf32(float* c,
                                         uint32_t a0, uint32_t a1, uint32_t a2, uint32_t a3,
                                         uint32_t b0, uint32_t b1) {
    asm volatile(
        "mma.sync.aligned.m16n8k8.row.col.f32.tf32.tf32.f32 "
        "{%0,%1,%2,%3}, {%4,%5,%6,%7}, {%8,%9}, {%0,%1,%2,%3};"
        : "+f"(c[0]), "+f"(c[1]), "+f"(c[2]), "+f"(c[3])
        : "r"(a0), "r"(a1), "r"(a2), "r"(a3), "r"(b0), "r"(b1));
}

// =================== tf32 mma.sync GEMM (software-pipelined) ===================
// C[m,n] = sum_k A[m,k]*B[n,k] + bias[n]; A (M,K), B (N,K) row-major fp32
// Block: 128x128x16, 8 warps, warp tile 64x32 (4x4 m16n8k8 frags)
// STRIDE 136: bank(addr) = (8*k + m) mod 32 -> all fragment loads conflict-free
#define BM 128
#define BN 128
#define BK 16
#define ASTRIDE 136
#define BSTRIDE 136

__global__ __launch_bounds__(256, 2) void gemm_mma_kernel(
    const float* __restrict__ A, const float* __restrict__ Bm,
    const float* __restrict__ bias, float* __restrict__ C,
    int M, int N, int K)
{
    __shared__ uint32_t As[BK][ASTRIDE];   // tf32 bits, k-major
    __shared__ uint32_t Bs[BK][BSTRIDE];

    const int tid = threadIdx.x;
    const int wid = tid >> 5;
    const int lane = tid & 31;
    const int bm = blockIdx.y * BM;
    const int bn = blockIdx.x * BN;

    const int warp_m = (wid >> 2) * 64;    // 0 or 64
    const int warp_n = (wid & 3) * 32;     // 0,32,64,96

    float acc[4][4][4];
#pragma unroll
    for (int i = 0; i < 4; i++)
#pragma unroll
        for (int j = 0; j < 4; j++)
#pragma unroll
            for (int r = 0; r < 4; r++) acc[i][j][r] = 0.f;

    // global load mapping: row = tid>>1 (0..127), lcol = (tid&1)*8
    const int grow = tid >> 1;
    const int lcol = (tid & 1) * 8;
    const float* Aptr = A + (size_t)(bm + grow) * K + lcol;
    const float* Bptr = Bm + (size_t)(bn + grow) * K + lcol;

    const int lq = lane >> 2;   // 0..7
    const int lr = lane & 3;    // 0..3

    // prefetch k-chunk 0
    float4 a0 = *(const float4*)(Aptr);
    float4 a1 = *(const float4*)(Aptr + 4);
    float4 b0 = *(const float4*)(Bptr);
    float4 b1 = *(const float4*)(Bptr + 4);

    const int NK = K / BK;
    for (int it = 0; it < NK; it++) {
        // SMEM is free here (first iter, or post-MMA sync of previous iter)
        As[lcol + 0][grow] = f2tf32(a0.x); As[lcol + 1][grow] = f2tf32(a0.y);
        As[lcol + 2][grow] = f2tf32(a0.z); As[lcol + 3][grow] = f2tf32(a0.w);
        As[lcol + 4][grow] = f2tf32(a1.x); As[lcol + 5][grow] = f2tf32(a1.y);
        As[lcol + 6][grow] = f2tf32(a1.z); As[lcol + 7][grow] = f2tf32(a1.w);
        Bs[lcol + 0][grow] = f2tf32(b0.x); Bs[lcol + 1][grow] = f2tf32(b0.y);
        Bs[lcol + 2][grow] = f2tf32(b0.z); Bs[lcol + 3][grow] = f2tf32(b0.w);
        Bs[lcol + 4][grow] = f2tf32(b1.x); Bs[lcol + 5][grow] = f2tf32(b1.y);
        Bs[lcol + 6][grow] = f2tf32(b1.z); Bs[lcol + 7][grow] = f2tf32(b1.w);
        __syncthreads();

        // issue next iter's global loads NOW; they drain under the MMA phase
        if (it + 1 < NK) {
            const float* An = Aptr + (it + 1) * BK;
            const float* Bn = Bptr + (it + 1) * BK;
            a0 = *(const float4*)(An);
            a1 = *(const float4*)(An + 4);
            b0 = *(const float4*)(Bn);
            b1 = *(const float4*)(Bn + 4);
        }

#pragma unroll
        for (int ks = 0; ks < BK; ks += 8) {
            // A fragments: a0=(r,c) a1=(r+8,c) a2=(r,c+4) a3=(r+8,c+4)
            uint32_t af[4][4];
#pragma unroll
            for (int mt = 0; mt < 4; mt++) {
                int r = warp_m + mt * 16 + lq;
                int c = ks + lr;
                af[mt][0] = As[c][r];
                af[mt][1] = As[c][r + 8];
                af[mt][2] = As[c + 4][r];
                af[mt][3] = As[c + 4][r + 8];
            }
            // B fragments (col-major k8n8): b0=(k,n) b1=(k+4,n)
            uint32_t bf[4][2];
#pragma unroll
            for (int nt = 0; nt < 4; nt++) {
                int n = warp_n + nt * 8 + lq;
                int k = ks + lr;
                bf[nt][0] = Bs[k][n];
                bf[nt][1] = Bs[k + 4][n];
            }
#pragma unroll
            for (int mt = 0; mt < 4; mt++)
#pragma unroll
                for (int nt = 0; nt < 4; nt++)
                    mma_tf32(acc[mt][nt], af[mt][0], af[mt][1], af[mt][2], af[mt][3],
                             bf[nt][0], bf[nt][1]);
        }
        __syncthreads();
    }

    // epilogue: frag layout c0=(r, 2c) c1=(r, 2c+1) c2=(r+8, 2c) c3=(r+8, 2c+1)
#pragma unroll
    for (int mt = 0; mt < 4; mt++) {
#pragma unroll
        for (int nt = 0; nt < 4; nt++) {
            int r0 = bm + warp_m + mt * 16 + lq;
            int c0 = bn + warp_n + nt * 8 + lr * 2;
            float bvx = bias[c0], bvy = bias[c0 + 1];
            float2 v0 = make_float2(acc[mt][nt][0] + bvx, acc[mt][nt][1] + bvy);
            float2 v1 = make_float2(acc[mt][nt][2] + bvx, acc[mt][nt][3] + bvy);
            *(float2*)(C + (size_t)r0 * N + c0) = v0;
            *(float2*)(C + (size_t)(r0 + 8) * N + c0) = v1;
        }
    }
}

// ---------------- RoPE (in-place) ----------------
__global__ void rope_kernel(float* __restrict__ X, const float* __restrict__ fr, int H)
{
    int idx = blockIdx.x * blockDim.x + threadIdx.x;
    int total = BZ * TT * H * (DD / 2);
    if (idx >= total) return;
    int j = idx % (DD / 2);
    int h = (idx / (DD / 2)) % H;
    int t = (idx / ((DD / 2) * H)) % TT;
    int b = idx / ((DD / 2) * H * TT);
    float c = fr[(t * (DD / 2) + j) * 2 + 0];
    float s = fr[(t * (DD / 2) + j) * 2 + 1];
    size_t base = (((size_t)b * TT + t) * H + h) * DD + 2 * j;
    float x0 = X[base], x1 = X[base + 1];
    X[base]     = x0 * c - x1 * s;
    X[base + 1] = x1 * c + x0 * s;
}

// ---------------- Flash attention (causal, GQA, fp32) ----------------
#define BQ 64
#define BKT 64
#define QSTRIDE 132
#define SSTRIDE 68
#define FLASH_SMEM_FLOATS (BQ*QSTRIDE + BKT*QSTRIDE + BKT*QSTRIDE + BQ*SSTRIDE + 3*BQ)
#define FLASH_SMEM_BYTES (FLASH_SMEM_FLOATS * 4)

__global__ __launch_bounds__(256) void flash_attn_kernel(
    const float* __restrict__ Q, const float* __restrict__ K,
    const float* __restrict__ V, float* __restrict__ Y)
{
    extern __shared__ float sm[];
    float* Qs = sm;
    float* Ks = Qs + BQ * QSTRIDE;
    float* Vs = Ks + BKT * QSTRIDE;
    float* Ss = Vs + BKT * QSTRIDE;
    float* fac  = Ss + BQ * SSTRIDE;
    float* mrow = fac + BQ;
    float* lrow = mrow + BQ;

    const int tid = threadIdx.x;
    const int tx = tid & 15;
    const int ty = tid >> 4;
    const int q0 = blockIdx.x * BQ;
    const int h  = blockIdx.y;
    const int b  = blockIdx.z;
    const int hk = h / GG;
    const float scale = rsqrtf((float)DD);

    for (int i = tid; i < BQ * (DD / 4); i += 256) {
        int r = i >> 5;
        int c4 = (i & 31) * 4;
        float4 v = *(const float4*)(Q + ((((size_t)b * TT + q0 + r) * HQ + h) * DD + c4));
        *(float4*)(Qs + r * QSTRIDE + c4) = v;
    }
    if (tid < BQ) { mrow[tid] = -1e30f; lrow[tid] = 0.f; }

    float o[4][8];
#pragma unroll
    for (int i = 0; i < 4; i++)
#pragma unroll
        for (int j = 0; j < 8; j++) o[i][j] = 0.f;

    const int ktiles = q0 / BKT + 1;
    for (int kt = 0; kt < ktiles; kt++) {
        const int k0 = kt * BKT;
        for (int i = tid; i < BKT * (DD / 4); i += 256) {
            int r = i >> 5;
            int c4 = (i & 31) * 4;
            size_t gidx = (((size_t)b * TT + k0 + r) * HKV + hk) * DD + c4;
            *(float4*)(Ks + r * QSTRIDE + c4) = *(const float4*)(K + gidx);
            *(float4*)(Vs + r * QSTRIDE + c4) = *(const float4*)(V + gidx);
        }
        __syncthreads();

        float s[4][4];
#pragma unroll
        for (int i = 0; i < 4; i++)
#pragma unroll
            for (int j = 0; j < 4; j++) s[i][j] = 0.f;

        for (int d4 = 0; d4 < DD; d4 += 4) {
            float4 qv[4], kv[4];
#pragma unroll
            for (int i = 0; i < 4; i++) qv[i] = *(const float4*)(Qs + (ty * 4 + i) * QSTRIDE + d4);
#pragma unroll
            for (int j = 0; j < 4; j++) kv[j] = *(const float4*)(Ks + (tx * 4 + j) * QSTRIDE + d4);
#pragma unroll
            for (int i = 0; i < 4; i++)
#pragma unroll
                for (int j = 0; j < 4; j++) {
                    s[i][j] = fmaf(qv[i].x, kv[j].x, s[i][j]);
                    s[i][j] = fmaf(qv[i].y, kv[j].y, s[i][j]);
                    s[i][j] = fmaf(qv[i].z, kv[j].z, s[i][j]);
                    s[i][j] = fmaf(qv[i].w, kv[j].w, s[i][j]);
                }
        }
#pragma unroll
        for (int i = 0; i < 4; i++)
#pragma unroll
            for (int j = 0; j < 4; j++) {
                float val = s[i][j] * scale;
                if (k0 + tx * 4 + j > q0 + ty * 4 + i) val = -1e30f;
                Ss[(ty * 4 + i) * SSTRIDE + tx * 4 + j] = val;
            }
        __syncthreads();

        if (tid < BQ) {
            int r = tid;
            float mo = mrow[r];
            float mx = mo;
            for (int c = 0; c < BKT; c++) mx = fmaxf(mx, Ss[r * SSTRIDE + c]);
            float sum = 0.f;
            for (int c = 0; c < BKT; c++) {
                float p = __expf(Ss[r * SSTRIDE + c] - mx);
                Ss[r * SSTRIDE + c] = p;
                sum += p;
            }
            float f = __expf(mo - mx);
            lrow[r] = lrow[r] * f + sum;
            mrow[r] = mx;
            fac[r] = f;
        }
        __syncthreads();

#pragma unroll
        for (int i = 0; i < 4; i++) {
            float f = fac[ty * 4 + i];
#pragma unroll
            for (int j = 0; j < 8; j++) o[i][j] *= f;
        }
        for (int k = 0; k < BKT; k++) {
            float4 v0 = *(const float4*)(Vs + k * QSTRIDE + tx * 8);
            float4 v1 = *(const float4*)(Vs + k * QSTRIDE + tx * 8 + 4);
#pragma unroll
            for (int i = 0; i < 4; i++) {
                float p = Ss[(ty * 4 + i) * SSTRIDE + k];
                o[i][0] = fmaf(p, v0.x, o[i][0]);
                o[i][1] = fmaf(p, v0.y, o[i][1]);
                o[i][2] = fmaf(p, v0.z, o[i][2]);
                o[i][3] = fmaf(p, v0.w, o[i][3]);
                o[i][4] = fmaf(p, v1.x, o[i][4]);
                o[i][5] = fmaf(p, v1.y, o[i][5]);
                o[i][6] = fmaf(p, v1.z, o[i][6]);
                o[i][7] = fmaf(p, v1.w, o[i][7]);
            }
        }
        __syncthreads();
    }

#pragma unroll
    for (int i = 0; i < 4; i++) {
        float inv = 1.f / lrow[ty * 4 + i];
        float* yp = Y + ((((size_t)b * TT + q0 + ty * 4 + i) * HQ + h) * DD + tx * 8);
        float4 o0, o1;
        o0.x = o[i][0] * inv; o0.y = o[i][1] * inv; o0.z = o[i][2] * inv; o0.w = o[i][3] * inv;
        o1.x = o[i][4] * inv; o1.y = o[i][5] * inv; o1.z = o[i][6] * inv; o1.w = o[i][7] * inv;
        *(float4*)(yp) = o0;
        *(float4*)(yp + 4) = o1;
    }
}

// ---------------- launch ----------------
extern "C" void kernel_launch(void* const* d_in, const int* in_sizes, int n_in,
                              void* d_out, int out_size)
{
    const float* query = (const float*)d_in[0];
    const float* key   = (const float*)d_in[1];
    const float* value = (const float*)d_in[2];
    const float* freqs = (const float*)d_in[3];
    const float* Wq = (const float*)d_in[5];
    const float* bq = (const float*)d_in[6];
    const float* Wk = (const float*)d_in[7];
    const float* bk = (const float*)d_in[8];
    const float* Wv = (const float*)d_in[9];
    const float* bv = (const float*)d_in[10];
    const float* Wo = (const float*)d_in[11];
    const float* bo = (const float*)d_in[12];
    float* out = (float*)d_out;

    float *Qb, *Kb, *Vb, *Yb;
    cudaGetSymbolAddress((void**)&Qb, g_Q);
    cudaGetSymbolAddress((void**)&Kb, g_K);
    cudaGetSymbolAddress((void**)&Vb, g_V);
    cudaGetSymbolAddress((void**)&Yb, g_Y);

    cudaFuncSetAttribute(flash_attn_kernel,
                         cudaFuncAttributeMaxDynamicSharedMemorySize, FLASH_SMEM_BYTES);

    dim3 blk(256);
    // projections (tf32 mma.sync tensor cores, pipelined)
    gemm_mma_kernel<<<dim3(EE / BN, MM / BM), blk>>>(query, Wq, bq, Qb, MM, EE, EE);
    gemm_mma_kernel<<<dim3(KVE / BN, MM / BM), blk>>>(key,   Wk, bk, Kb, MM, KVE, EE);
    gemm_mma_kernel<<<dim3(KVE / BN, MM / BM), blk>>>(value, Wv, bv, Vb, MM, KVE, EE);

    // RoPE
    {
        int totq = BZ * TT * HQ * (DD / 2);
        rope_kernel<<<(totq + 255) / 256, 256>>>(Qb, freqs, HQ);
        int totk = BZ * TT * HKV * (DD / 2);
        rope_kernel<<<(totk + 255) / 256, 256>>>(Kb, freqs, HKV);
    }

    // attention (fp32 flash)
    flash_attn_kernel<<<dim3(TT / BQ, HQ, BZ), 256, FLASH_SMEM_BYTES>>>(Qb, Kb, Vb, Yb);

    // output projection -> d_out (tf32 mma.sync, pipelined)
    gemm_mma_kernel<<<dim3(EE / BN, MM / BM), blk>>>(Yb, Wo, bo, out, MM, EE, EE);
}

// round 11
// speedup vs baseline: 1.8832x; 1.1257x over previous
#include <cuda_runtime.h>
#include <cuda_bf16.h>
#include <math.h>
#include <cstdint>

// Problem constants
#define BZ 2
#define TT 2048
#define EE 4096
#define HQ 32
#define HKV 8
#define DD 128
#define GG 4
#define MM (BZ * TT)          // 4096 rows
#define KVE (HKV * DD)        // 1024

// ---------------- scratch (no cudaMalloc allowed) ----------------
__device__ float g_Q[(size_t)MM * EE];    // 64 MB  (B,T,HQ,D)
__device__ float g_K[(size_t)MM * KVE];   // 16 MB  (B,T,HKV,D)
__device__ float g_V[(size_t)MM * KVE];   // 16 MB
__device__ float g_Y[(size_t)MM * EE];    // 64 MB  attention output (B,T,HQ,D)

__device__ __forceinline__ uint32_t f2tf32(float f) {
    uint32_t r;
    asm("cvt.rna.tf32.f32 %0, %1;" : "=r"(r) : "f"(f));
    return r;
}
__device__ __forceinline__ uint32_t smem_u32(const void* p) {
    uint32_t a;
    asm("{ .reg .u64 t; cvta.to.shared.u64 t, %1; cvt.u32.u64 %0, t; }" : "=r"(a) : "l"(p));
    return a;
}
__device__ __forceinline__ void cp16(uint32_t dst, const float* src) {
    asm volatile("cp.async.cg.shared.global [%0], [%1], 16;" :: "r"(dst), "l"(src) : "memory");
}
#define CP_COMMIT() asm volatile("cp.async.commit_group;" ::: "memory")
#define CP_WAIT2()  asm volatile("cp.async.wait_group 2;" ::: "memory")

// tf32 warp MMA: D(16x8) += A(16x8) * B(8x8)
__device__ __forceinline__ void mma_tf32(float* c,
                                         uint32_t a0, uint32_t a1, uint32_t a2, uint32_t a3,
                                         uint32_t b0, uint32_t b1) {
    asm volatile(
        "mma.sync.aligned.m16n8k8.row.col.f32.tf32.tf32.f32 "
        "{%0,%1,%2,%3}, {%4,%5,%6,%7}, {%8,%9}, {%0,%1,%2,%3};"
        : "+f"(c[0]), "+f"(c[1]), "+f"(c[2]), "+f"(c[3])
        : "r"(a0), "r"(a1), "r"(a2), "r"(a3), "r"(b0), "r"(b1));
}

// =================== tf32 mma.sync GEMM (4-stage cp.async pipeline) ===================
// C[m,n] = sum_k A[m,k]*B[n,k] + bias[n]; A (M,K), B (N,K) row-major fp32
// Block 128x128x16, 8 warps, warp tile 64x32. SMEM holds raw fp32 in global (m-major)
// layout, rows padded to 20 floats: banks (20r + c) mod 32 are conflict-free for frags.
#define BM 128
#define BN 128
#define BK 16
#define ROWF 20
#define HALF_STAGE (128 * ROWF)             // A part (floats)
#define STAGE_FLOATS (2 * HALF_STAGE)       // A then B
#define NSTAGE 4
#define GEMM_SMEM_BYTES (NSTAGE * STAGE_FLOATS * 4)   // 81920

__global__ __launch_bounds__(256) void gemm_mma_kernel(
    const float* __restrict__ A, const float* __restrict__ Bm,
    const float* __restrict__ bias, float* __restrict__ C,
    int M, int N, int K)
{
    extern __shared__ float smem[];
    const uint32_t smem_base = smem_u32(smem);

    const int tid = threadIdx.x;
    const int wid = tid >> 5;
    const int lane = tid & 31;
    const int bm = blockIdx.y * BM;
    const int bn = blockIdx.x * BN;

    const int warp_m = (wid >> 2) * 64;    // 0 or 64
    const int warp_n = (wid & 3) * 32;     // 0,32,64,96
    const int lq = lane >> 2;   // 0..7
    const int lr = lane & 3;    // 0..3

    float acc[4][4][4];
#pragma unroll
    for (int i = 0; i < 4; i++)
#pragma unroll
        for (int j = 0; j < 4; j++)
#pragma unroll
            for (int r = 0; r < 4; r++) acc[i][j][r] = 0.f;

    // copy mapping: 512 16B-chunks per matrix per stage; thread does 2 A + 2 B chunks
    // chunk ch: row = ch>>2 (0..127), kq = ch&3 (16B quarter of the 64B row)
    const int ch0 = tid * 2;
    const int r0c = ch0 >> 2, kq0 = ch0 & 3;
    const int r1c = (ch0 + 1) >> 2, kq1 = (ch0 + 1) & 3;
    const float* Arow0 = A + (size_t)(bm + r0c) * K + kq0 * 4;
    const float* Arow1 = A + (size_t)(bm + r1c) * K + kq1 * 4;
    const float* Brow0 = Bm + (size_t)(bn + r0c) * K + kq0 * 4;
    const float* Brow1 = Bm + (size_t)(bn + r1c) * K + kq1 * 4;
    const uint32_t sa_off0 = (uint32_t)(r0c * ROWF + kq0 * 4) * 4;
    const uint32_t sa_off1 = (uint32_t)(r1c * ROWF + kq1 * 4) * 4;

    const int NK = K / BK;

#define ISSUE_STAGE(it, slot) do {                                           \
        uint32_t sbase = smem_base + (uint32_t)(slot) * (STAGE_FLOATS * 4);  \
        uint32_t bbase = sbase + HALF_STAGE * 4;                             \
        int koff = (it) * BK;                                                \
        cp16(sbase + sa_off0, Arow0 + koff);                                 \
        cp16(sbase + sa_off1, Arow1 + koff);                                 \
        cp16(bbase + sa_off0, Brow0 + koff);                                 \
        cp16(bbase + sa_off1, Brow1 + koff);                                 \
    } while (0)

    // prologue: stages 0..2 in flight
#pragma unroll
    for (int s = 0; s < NSTAGE - 1; s++) {
        if (s < NK) ISSUE_STAGE(s, s);
        CP_COMMIT();
    }

    for (int it = 0; it < NK; it++) {
        CP_WAIT2();            // stage it arrived (<=2 groups pending)
        __syncthreads();       // visible to all warps; slot (it-1)&3 free for reuse

        int nxt = it + NSTAGE - 1;
        if (nxt < NK) ISSUE_STAGE(nxt, nxt & 3);
        CP_COMMIT();

        const float* sa = smem + (it & 3) * STAGE_FLOATS;
        const float* sb = sa + HALF_STAGE;

#pragma unroll
        for (int ks = 0; ks < BK; ks += 8) {
            uint32_t af[4][4];
#pragma unroll
            for (int mt = 0; mt < 4; mt++) {
                int r = warp_m + mt * 16 + lq;
                int c = ks + lr;
                af[mt][0] = f2tf32(sa[r * ROWF + c]);
                af[mt][1] = f2tf32(sa[(r + 8) * ROWF + c]);
                af[mt][2] = f2tf32(sa[r * ROWF + c + 4]);
                af[mt][3] = f2tf32(sa[(r + 8) * ROWF + c + 4]);
            }
            uint32_t bf[4][2];
#pragma unroll
            for (int nt = 0; nt < 4; nt++) {
                int n = warp_n + nt * 8 + lq;
                int k = ks + lr;
                bf[nt][0] = f2tf32(sb[n * ROWF + k]);
                bf[nt][1] = f2tf32(sb[n * ROWF + k + 4]);
            }
#pragma unroll
            for (int mt = 0; mt < 4; mt++)
#pragma unroll
                for (int nt = 0; nt < 4; nt++)
                    mma_tf32(acc[mt][nt], af[mt][0], af[mt][1], af[mt][2], af[mt][3],
                             bf[nt][0], bf[nt][1]);
        }
    }

    // epilogue: frag layout c0=(r, 2c) c1=(r, 2c+1) c2=(r+8, 2c) c3=(r+8, 2c+1)
#pragma unroll
    for (int mt = 0; mt < 4; mt++) {
#pragma unroll
        for (int nt = 0; nt < 4; nt++) {
            int r0 = bm + warp_m + mt * 16 + lq;
            int c0 = bn + warp_n + nt * 8 + lr * 2;
            float bvx = bias[c0], bvy = bias[c0 + 1];
            float2 v0 = make_float2(acc[mt][nt][0] + bvx, acc[mt][nt][1] + bvy);
            float2 v1 = make_float2(acc[mt][nt][2] + bvx, acc[mt][nt][3] + bvy);
            *(float2*)(C + (size_t)r0 * N + c0) = v0;
            *(float2*)(C + (size_t)(r0 + 8) * N + c0) = v1;
        }
    }
#undef ISSUE_STAGE
}

// ---------------- RoPE (in-place) ----------------
__global__ void rope_kernel(float* __restrict__ X, const float* __restrict__ fr, int H)
{
    int idx = blockIdx.x * blockDim.x + threadIdx.x;
    int total = BZ * TT * H * (DD / 2);
    if (idx >= total) return;
    int j = idx % (DD / 2);
    int h = (idx / (DD / 2)) % H;
    int t = (idx / ((DD / 2) * H)) % TT;
    int b = idx / ((DD / 2) * H * TT);
    float c = fr[(t * (DD / 2) + j) * 2 + 0];
    float s = fr[(t * (DD / 2) + j) * 2 + 1];
    size_t base = (((size_t)b * TT + t) * H + h) * DD + 2 * j;
    float x0 = X[base], x1 = X[base + 1];
    X[base]     = x0 * c - x1 * s;
    X[base + 1] = x1 * c + x0 * s;
}

// ---------------- Flash attention (causal, GQA, fp32) ----------------
#define BQ 64
#define BKT 64
#define QSTRIDE 132
#define SSTRIDE 68
#define FLASH_SMEM_FLOATS (BQ*QSTRIDE + BKT*QSTRIDE + BKT*QSTRIDE + BQ*SSTRIDE + 3*BQ)
#define FLASH_SMEM_BYTES (FLASH_SMEM_FLOATS * 4)

__global__ __launch_bounds__(256) void flash_attn_kernel(
    const float* __restrict__ Q, const float* __restrict__ K,
    const float* __restrict__ V, float* __restrict__ Y)
{
    extern __shared__ float sm[];
    float* Qs = sm;
    float* Ks = Qs + BQ * QSTRIDE;
    float* Vs = Ks + BKT * QSTRIDE;
    float* Ss = Vs + BKT * QSTRIDE;
    float* fac  = Ss + BQ * SSTRIDE;
    float* mrow = fac + BQ;
    float* lrow = mrow + BQ;

    const int tid = threadIdx.x;
    const int tx = tid & 15;
    const int ty = tid >> 4;
    const int q0 = blockIdx.x * BQ;
    const int h  = blockIdx.y;
    const int b  = blockIdx.z;
    const int hk = h / GG;
    const float scale = rsqrtf((float)DD);

    for (int i = tid; i < BQ * (DD / 4); i += 256) {
        int r = i >> 5;
        int c4 = (i & 31) * 4;
        float4 v = *(const float4*)(Q + ((((size_t)b * TT + q0 + r) * HQ + h) * DD + c4));
        *(float4*)(Qs + r * QSTRIDE + c4) = v;
    }
    if (tid < BQ) { mrow[tid] = -1e30f; lrow[tid] = 0.f; }

    float o[4][8];
#pragma unroll
    for (int i = 0; i < 4; i++)
#pragma unroll
        for (int j = 0; j < 8; j++) o[i][j] = 0.f;

    const int ktiles = q0 / BKT + 1;
    for (int kt = 0; kt < ktiles; kt++) {
        const int k0 = kt * BKT;
        for (int i = tid; i < BKT * (DD / 4); i += 256) {
            int r = i >> 5;
            int c4 = (i & 31) * 4;
            size_t gidx = (((size_t)b * TT + k0 + r) * HKV + hk) * DD + c4;
            *(float4*)(Ks + r * QSTRIDE + c4) = *(const float4*)(K + gidx);
            *(float4*)(Vs + r * QSTRIDE + c4) = *(const float4*)(V + gidx);
        }
        __syncthreads();

        float s[4][4];
#pragma unroll
        for (int i = 0; i < 4; i++)
#pragma unroll
            for (int j = 0; j < 4; j++) s[i][j] = 0.f;

        for (int d4 = 0; d4 < DD; d4 += 4) {
            float4 qv[4], kv[4];
#pragma unroll
            for (int i = 0; i < 4; i++) qv[i] = *(const float4*)(Qs + (ty * 4 + i) * QSTRIDE + d4);
#pragma unroll
            for (int j = 0; j < 4; j++) kv[j] = *(const float4*)(Ks + (tx * 4 + j) * QSTRIDE + d4);
#pragma unroll
            for (int i = 0; i < 4; i++)
#pragma unroll
                for (int j = 0; j < 4; j++) {
                    s[i][j] = fmaf(qv[i].x, kv[j].x, s[i][j]);
                    s[i][j] = fmaf(qv[i].y, kv[j].y, s[i][j]);
                    s[i][j] = fmaf(qv[i].z, kv[j].z, s[i][j]);
                    s[i][j] = fmaf(qv[i].w, kv[j].w, s[i][j]);
                }
        }
#pragma unroll
        for (int i = 0; i < 4; i++)
#pragma unroll
            for (int j = 0; j < 4; j++) {
                float val = s[i][j] * scale;
                if (k0 + tx * 4 + j > q0 + ty * 4 + i) val = -1e30f;
                Ss[(ty * 4 + i) * SSTRIDE + tx * 4 + j] = val;
            }
        __syncthreads();

        if (tid < BQ) {
            int r = tid;
            float mo = mrow[r];
            float mx = mo;
            for (int c = 0; c < BKT; c++) mx = fmaxf(mx, Ss[r * SSTRIDE + c]);
            float sum = 0.f;
            for (int c = 0; c < BKT; c++) {
                float p = __expf(Ss[r * SSTRIDE + c] - mx);
                Ss[r * SSTRIDE + c] = p;
                sum += p;
            }
            float f = __expf(mo - mx);
            lrow[r] = lrow[r] * f + sum;
            mrow[r] = mx;
            fac[r] = f;
        }
        __syncthreads();

#pragma unroll
        for (int i = 0; i < 4; i++) {
            float f = fac[ty * 4 + i];
#pragma unroll
            for (int j = 0; j < 8; j++) o[i][j] *= f;
        }
        for (int k = 0; k < BKT; k++) {
            float4 v0 = *(const float4*)(Vs + k * QSTRIDE + tx * 8);
            float4 v1 = *(const float4*)(Vs + k * QSTRIDE + tx * 8 + 4);
#pragma unroll
            for (int i = 0; i < 4; i++) {
                float p = Ss[(ty * 4 + i) * SSTRIDE + k];
                o[i][0] = fmaf(p, v0.x, o[i][0]);
                o[i][1] = fmaf(p, v0.y, o[i][1]);
                o[i][2] = fmaf(p, v0.z, o[i][2]);
                o[i][3] = fmaf(p, v0.w, o[i][3]);
                o[i][4] = fmaf(p, v1.x, o[i][4]);
                o[i][5] = fmaf(p, v1.y, o[i][5]);
                o[i][6] = fmaf(p, v1.z, o[i][6]);
                o[i][7] = fmaf(p, v1.w, o[i][7]);
            }
        }
        __syncthreads();
    }

#pragma unroll
    for (int i = 0; i < 4; i++) {
        float inv = 1.f / lrow[ty * 4 + i];
        float* yp = Y + ((((size_t)b * TT + q0 + ty * 4 + i) * HQ + h) * DD + tx * 8);
        float4 o0, o1;
        o0.x = o[i][0] * inv; o0.y = o[i][1] * inv; o0.z = o[i][2] * inv; o0.w = o[i][3] * inv;
        o1.x = o[i][4] * inv; o1.y = o[i][5] * inv; o1.z = o[i][6] * inv; o1.w = o[i][7] * inv;
        *(float4*)(yp) = o0;
        *(float4*)(yp + 4) = o1;
    }
}

// ---------------- launch ----------------
extern "C" void kernel_launch(void* const* d_in, const int* in_sizes, int n_in,
                              void* d_out, int out_size)
{
    const float* query = (const float*)d_in[0];
    const float* key   = (const float*)d_in[1];
    const float* value = (const float*)d_in[2];
    const float* freqs = (const float*)d_in[3];
    const float* Wq = (const float*)d_in[5];
    const float* bq = (const float*)d_in[6];
    const float* Wk = (const float*)d_in[7];
    const float* bk = (const float*)d_in[8];
    const float* Wv = (const float*)d_in[9];
    const float* bv = (const float*)d_in[10];
    const float* Wo = (const float*)d_in[11];
    const float* bo = (const float*)d_in[12];
    float* out = (float*)d_out;

    float *Qb, *Kb, *Vb, *Yb;
    cudaGetSymbolAddress((void**)&Qb, g_Q);
    cudaGetSymbolAddress((void**)&Kb, g_K);
    cudaGetSymbolAddress((void**)&Vb, g_V);
    cudaGetSymbolAddress((void**)&Yb, g_Y);

    cudaFuncSetAttribute(gemm_mma_kernel,
                         cudaFuncAttributeMaxDynamicSharedMemorySize, GEMM_SMEM_BYTES);
    cudaFuncSetAttribute(flash_attn_kernel,
                         cudaFuncAttributeMaxDynamicSharedMemorySize, FLASH_SMEM_BYTES);

    dim3 blk(256);
    // projections (tf32 mma.sync, 4-stage cp.async pipeline)
    gemm_mma_kernel<<<dim3(EE / BN, MM / BM), blk, GEMM_SMEM_BYTES>>>(query, Wq, bq, Qb, MM, EE, EE);
    gemm_mma_kernel<<<dim3(KVE / BN, MM / BM), blk, GEMM_SMEM_BYTES>>>(key,   Wk, bk, Kb, MM, KVE, EE);
    gemm_mma_kernel<<<dim3(KVE / BN, MM / BM), blk, GEMM_SMEM_BYTES>>>(value, Wv, bv, Vb, MM, KVE, EE);

    // RoPE
    {
        int totq = BZ * TT * HQ * (DD / 2);
        rope_kernel<<<(totq + 255) / 256, 256>>>(Qb, freqs, HQ);
        int totk = BZ * TT * HKV * (DD / 2);
        rope_kernel<<<(totk + 255) / 256, 256>>>(Kb, freqs, HKV);
    }

    // attention (fp32 flash)
    flash_attn_kernel<<<dim3(TT / BQ, HQ, BZ), 256, FLASH_SMEM_BYTES>>>(Qb, Kb, Vb, Yb);

    // output projection -> d_out (tf32 mma.sync, pipelined)
    gemm_mma_kernel<<<dim3(EE / BN, MM / BM), blk, GEMM_SMEM_BYTES>>>(Yb, Wo, bo, out, MM, EE, EE);
}

// round 12
// speedup vs baseline: 3.1404x; 1.6676x over previous
#include <cuda_runtime.h>
#include <cuda_bf16.h>
#include <math.h>
#include <cstdint>

// Problem constants
#define BZ 2
#define TT 2048
#define EE 4096
#define HQ 32
#define HKV 8
#define DD 128
#define GG 4
#define MM (BZ * TT)          // 4096 rows
#define KVE (HKV * DD)        // 1024

// ---------------- scratch (no cudaMalloc allowed) ----------------
__device__ float g_Q[(size_t)MM * EE];    // 64 MB  (B,T,HQ,D)
__device__ float g_K[(size_t)MM * KVE];   // 16 MB  (B,T,HKV,D)
__device__ float g_V[(size_t)MM * KVE];   // 16 MB
__device__ float g_Y[(size_t)MM * EE];    // 64 MB  attention output (B,T,HQ,D)

__device__ __forceinline__ uint32_t f2tf32(float f) {
    uint32_t r;
    asm("cvt.rna.tf32.f32 %0, %1;" : "=r"(r) : "f"(f));
    return r;
}
__device__ __forceinline__ uint32_t smem_u32(const void* p) {
    uint32_t a;
    asm("{ .reg .u64 t; cvta.to.shared.u64 t, %1; cvt.u32.u64 %0, t; }" : "=r"(a) : "l"(p));
    return a;
}
__device__ __forceinline__ void cp16(uint32_t dst, const float* src) {
    asm volatile("cp.async.cg.shared.global [%0], [%1], 16;" :: "r"(dst), "l"(src) : "memory");
}
#define CP_COMMIT() asm volatile("cp.async.commit_group;" ::: "memory")
#define CP_WAIT2()  asm volatile("cp.async.wait_group 2;" ::: "memory")

// tf32 warp MMA: D(16x8) += A(16x8) * B(8x8)
__device__ __forceinline__ void mma_tf32(float* c,
                                         uint32_t a0, uint32_t a1, uint32_t a2, uint32_t a3,
                                         uint32_t b0, uint32_t b1) {
    asm volatile(
        "mma.sync.aligned.m16n8k8.row.col.f32.tf32.tf32.f32 "
        "{%0,%1,%2,%3}, {%4,%5,%6,%7}, {%8,%9}, {%0,%1,%2,%3};"
        : "+f"(c[0]), "+f"(c[1]), "+f"(c[2]), "+f"(c[3])
        : "r"(a0), "r"(a1), "r"(a2), "r"(a3), "r"(b0), "r"(b1));
}

// =================== tf32 mma.sync GEMM (4-stage cp.async pipeline) ===================
#define BM 128
#define BN 128
#define BK 16
#define ROWF 20
#define HALF_STAGE (128 * ROWF)
#define STAGE_FLOATS (2 * HALF_STAGE)
#define NSTAGE 4
#define GEMM_SMEM_BYTES (NSTAGE * STAGE_FLOATS * 4)   // 81920

__global__ __launch_bounds__(256) void gemm_mma_kernel(
    const float* __restrict__ A, const float* __restrict__ Bm,
    const float* __restrict__ bias, float* __restrict__ C,
    int M, int N, int K)
{
    extern __shared__ float smem[];
    const uint32_t smem_base = smem_u32(smem);

    const int tid = threadIdx.x;
    const int wid = tid >> 5;
    const int lane = tid & 31;
    const int bm = blockIdx.y * BM;
    const int bn = blockIdx.x * BN;

    const int warp_m = (wid >> 2) * 64;
    const int warp_n = (wid & 3) * 32;
    const int lq = lane >> 2;
    const int lr = lane & 3;

    float acc[4][4][4];
#pragma unroll
    for (int i = 0; i < 4; i++)
#pragma unroll
        for (int j = 0; j < 4; j++)
#pragma unroll
            for (int r = 0; r < 4; r++) acc[i][j][r] = 0.f;

    const int ch0 = tid * 2;
    const int r0c = ch0 >> 2, kq0 = ch0 & 3;
    const int r1c = (ch0 + 1) >> 2, kq1 = (ch0 + 1) & 3;
    const float* Arow0 = A + (size_t)(bm + r0c) * K + kq0 * 4;
    const float* Arow1 = A + (size_t)(bm + r1c) * K + kq1 * 4;
    const float* Brow0 = Bm + (size_t)(bn + r0c) * K + kq0 * 4;
    const float* Brow1 = Bm + (size_t)(bn + r1c) * K + kq1 * 4;
    const uint32_t sa_off0 = (uint32_t)(r0c * ROWF + kq0 * 4) * 4;
    const uint32_t sa_off1 = (uint32_t)(r1c * ROWF + kq1 * 4) * 4;

    const int NK = K / BK;

#define ISSUE_STAGE(it, slot) do {                                           \
        uint32_t sbase = smem_base + (uint32_t)(slot) * (STAGE_FLOATS * 4);  \
        uint32_t bbase = sbase + HALF_STAGE * 4;                             \
        int koff = (it) * BK;                                                \
        cp16(sbase + sa_off0, Arow0 + koff);                                 \
        cp16(sbase + sa_off1, Arow1 + koff);                                 \
        cp16(bbase + sa_off0, Brow0 + koff);                                 \
        cp16(bbase + sa_off1, Brow1 + koff);                                 \
    } while (0)

#pragma unroll
    for (int s = 0; s < NSTAGE - 1; s++) {
        if (s < NK) ISSUE_STAGE(s, s);
        CP_COMMIT();
    }

    for (int it = 0; it < NK; it++) {
        CP_WAIT2();
        __syncthreads();

        int nxt = it + NSTAGE - 1;
        if (nxt < NK) ISSUE_STAGE(nxt, nxt & 3);
        CP_COMMIT();

        const float* sa = smem + (it & 3) * STAGE_FLOATS;
        const float* sb = sa + HALF_STAGE;

#pragma unroll
        for (int ks = 0; ks < BK; ks += 8) {
            uint32_t af[4][4];
#pragma unroll
            for (int mt = 0; mt < 4; mt++) {
                int r = warp_m + mt * 16 + lq;
                int c = ks + lr;
                af[mt][0] = f2tf32(sa[r * ROWF + c]);
                af[mt][1] = f2tf32(sa[(r + 8) * ROWF + c]);
                af[mt][2] = f2tf32(sa[r * ROWF + c + 4]);
                af[mt][3] = f2tf32(sa[(r + 8) * ROWF + c + 4]);
            }
            uint32_t bf[4][2];
#pragma unroll
            for (int nt = 0; nt < 4; nt++) {
                int n = warp_n + nt * 8 + lq;
                int k = ks + lr;
                bf[nt][0] = f2tf32(sb[n * ROWF + k]);
                bf[nt][1] = f2tf32(sb[n * ROWF + k + 4]);
            }
#pragma unroll
            for (int mt = 0; mt < 4; mt++)
#pragma unroll
                for (int nt = 0; nt < 4; nt++)
                    mma_tf32(acc[mt][nt], af[mt][0], af[mt][1], af[mt][2], af[mt][3],
                             bf[nt][0], bf[nt][1]);
        }
    }

#pragma unroll
    for (int mt = 0; mt < 4; mt++) {
#pragma unroll
        for (int nt = 0; nt < 4; nt++) {
            int r0 = bm + warp_m + mt * 16 + lq;
            int c0 = bn + warp_n + nt * 8 + lr * 2;
            float bvx = bias[c0], bvy = bias[c0 + 1];
            float2 v0 = make_float2(acc[mt][nt][0] + bvx, acc[mt][nt][1] + bvy);
            float2 v1 = make_float2(acc[mt][nt][2] + bvx, acc[mt][nt][3] + bvy);
            *(float2*)(C + (size_t)r0 * N + c0) = v0;
            *(float2*)(C + (size_t)(r0 + 8) * N + c0) = v1;
        }
    }
#undef ISSUE_STAGE
}

// ---------------- RoPE (in-place) ----------------
__global__ void rope_kernel(float* __restrict__ X, const float* __restrict__ fr, int H)
{
    int idx = blockIdx.x * blockDim.x + threadIdx.x;
    int total = BZ * TT * H * (DD / 2);
    if (idx >= total) return;
    int j = idx % (DD / 2);
    int h = (idx / (DD / 2)) % H;
    int t = (idx / ((DD / 2) * H)) % TT;
    int b = idx / ((DD / 2) * H * TT);
    float c = fr[(t * (DD / 2) + j) * 2 + 0];
    float s = fr[(t * (DD / 2) + j) * 2 + 1];
    size_t base = (((size_t)b * TT + t) * H + h) * DD + 2 * j;
    float x0 = X[base], x1 = X[base + 1];
    X[base]     = x0 * c - x1 * s;
    X[base + 1] = x1 * c + x0 * s;
}

// ---------------- Flash attention (causal, GQA, tf32 mma + parallel softmax) ----------------
#define BQ 64
#define BKT 64
#define QSTR 136
#define SSTR 68
#define FLASH_SMEM_FLOATS (3 * BQ * QSTR + BQ * SSTR + 3 * BQ)
#define FLASH_SMEM_BYTES (FLASH_SMEM_FLOATS * 4)   // 122624

__global__ __launch_bounds__(256) void flash_attn_kernel(
    const float* __restrict__ Q, const float* __restrict__ K,
    const float* __restrict__ V, float* __restrict__ Y)
{
    extern __shared__ float sm[];
    float* Qs = sm;                       // [64][136]
    float* Ks = Qs + BQ * QSTR;           // [64][136]
    float* Vs = Ks + BKT * QSTR;          // [64][136]
    float* Ss = Vs + BKT * QSTR;          // [64][68]
    float* fac  = Ss + BQ * SSTR;
    float* mrow = fac + BQ;
    float* lrow = mrow + BQ;

    const int tid = threadIdx.x;
    const int wid = tid >> 5;
    const int lane = tid & 31;
    const int lq = lane >> 2;     // 0..7
    const int lr = lane & 3;      // 0..3

    const int r0  = (wid >> 1) * 16;   // warp's S/O row base (0,16,32,48)
    const int c0  = (wid & 1) * 32;    // warp's S col base  (0,32)
    const int oc0 = (wid & 1) * 64;    // warp's O col base  (0,64)

    const int q0 = blockIdx.x * BQ;
    const int h  = blockIdx.y;
    const int b  = blockIdx.z;
    const int hk = h / GG;
    const float scale = rsqrtf((float)DD);

    // load Q tile
    for (int i = tid; i < BQ * (DD / 4); i += 256) {
        int r = i >> 5;
        int c4 = (i & 31) * 4;
        float4 v = *(const float4*)(Q + ((((size_t)b * TT + q0 + r) * HQ + h) * DD + c4));
        *(float4*)(Qs + r * QSTR + c4) = v;
    }
    if (tid < BQ) { mrow[tid] = -1e30f; lrow[tid] = 0.f; }

    float oacc[8][4];
#pragma unroll
    for (int nt = 0; nt < 8; nt++)
#pragma unroll
        for (int r = 0; r < 4; r++) oacc[nt][r] = 0.f;

    const int ktiles = q0 / BKT + 1;
    for (int kt = 0; kt < ktiles; kt++) {
        const int k0 = kt * BKT;
        __syncthreads();   // previous iter's Ss/V reads done before overwrite
        for (int i = tid; i < BKT * (DD / 4); i += 256) {
            int r = i >> 5;
            int c4 = (i & 31) * 4;
            size_t gidx = (((size_t)b * TT + k0 + r) * HKV + hk) * DD + c4;
            *(float4*)(Ks + r * QSTR + c4) = *(const float4*)(K + gidx);
            *(float4*)(Vs + r * QSTR + c4) = *(const float4*)(V + gidx);
        }
        __syncthreads();

        // ---- S = Q K^T (tf32 mma) ----
        float sacc[4][4];
#pragma unroll
        for (int nt = 0; nt < 4; nt++)
#pragma unroll
            for (int r = 0; r < 4; r++) sacc[nt][r] = 0.f;

#pragma unroll
        for (int d = 0; d < DD; d += 8) {
            uint32_t a0 = f2tf32(Qs[(r0 + lq) * QSTR + d + lr]);
            uint32_t a1 = f2tf32(Qs[(r0 + lq + 8) * QSTR + d + lr]);
            uint32_t a2 = f2tf32(Qs[(r0 + lq) * QSTR + d + lr + 4]);
            uint32_t a3 = f2tf32(Qs[(r0 + lq + 8) * QSTR + d + lr + 4]);
#pragma unroll
            for (int nt = 0; nt < 4; nt++) {
                uint32_t b0 = f2tf32(Ks[(c0 + nt * 8 + lq) * QSTR + d + lr]);
                uint32_t b1 = f2tf32(Ks[(c0 + nt * 8 + lq) * QSTR + d + lr + 4]);
                mma_tf32(sacc[nt], a0, a1, a2, a3, b0, b1);
            }
        }
        // scale + causal mask + store to Ss
#pragma unroll
        for (int nt = 0; nt < 4; nt++) {
            int c = c0 + nt * 8 + lr * 2;
            int r = r0 + lq;
            float v0 = sacc[nt][0] * scale, v1 = sacc[nt][1] * scale;
            float v2 = sacc[nt][2] * scale, v3 = sacc[nt][3] * scale;
            if (k0 + c     > q0 + r)     v0 = -1e30f;
            if (k0 + c + 1 > q0 + r)     v1 = -1e30f;
            if (k0 + c     > q0 + r + 8) v2 = -1e30f;
            if (k0 + c + 1 > q0 + r + 8) v3 = -1e30f;
            *(float2*)(Ss + r * SSTR + c) = make_float2(v0, v1);
            *(float2*)(Ss + (r + 8) * SSTR + c) = make_float2(v2, v3);
        }
        __syncthreads();

        // ---- online softmax: 4 threads per row, all warps ----
        {
            int r = tid >> 2;
            int sub = tid & 3;
            float* row = Ss + r * SSTR + sub * 16;
            float mo = mrow[r];
            float mx = mo;
            float vals[16];
#pragma unroll
            for (int i = 0; i < 16; i++) { vals[i] = row[i]; mx = fmaxf(mx, vals[i]); }
            mx = fmaxf(mx, __shfl_xor_sync(0xFFFFFFFFu, mx, 1));
            mx = fmaxf(mx, __shfl_xor_sync(0xFFFFFFFFu, mx, 2));
            float sum = 0.f;
#pragma unroll
            for (int i = 0; i < 16; i++) {
                float p = __expf(vals[i] - mx);
                row[i] = p;
                sum += p;
            }
            sum += __shfl_xor_sync(0xFFFFFFFFu, sum, 1);
            sum += __shfl_xor_sync(0xFFFFFFFFu, sum, 2);
            if (sub == 0) {
                float f = __expf(mo - mx);
                lrow[r] = lrow[r] * f + sum;
                mrow[r] = mx;
                fac[r] = f;
            }
        }
        __syncthreads();

        // ---- O = O*fac + P V (tf32 mma) ----
        {
            float f0 = fac[r0 + lq];
            float f1 = fac[r0 + lq + 8];
#pragma unroll
            for (int nt = 0; nt < 8; nt++) {
                oacc[nt][0] *= f0; oacc[nt][1] *= f0;
                oacc[nt][2] *= f1; oacc[nt][3] *= f1;
            }
        }
#pragma unroll
        for (int ks = 0; ks < BKT; ks += 8) {
            uint32_t a0 = f2tf32(Ss[(r0 + lq) * SSTR + ks + lr]);
            uint32_t a1 = f2tf32(Ss[(r0 + lq + 8) * SSTR + ks + lr]);
            uint32_t a2 = f2tf32(Ss[(r0 + lq) * SSTR + ks + lr + 4]);
            uint32_t a3 = f2tf32(Ss[(r0 + lq + 8) * SSTR + ks + lr + 4]);
#pragma unroll
            for (int nt = 0; nt < 8; nt++) {
                uint32_t b0 = f2tf32(Vs[(ks + lr) * QSTR + oc0 + nt * 8 + lq]);
                uint32_t b1 = f2tf32(Vs[(ks + lr + 4) * QSTR + oc0 + nt * 8 + lq]);
                mma_tf32(oacc[nt], a0, a1, a2, a3, b0, b1);
            }
        }
    }

    // epilogue: divide by l, write (B,T,HQ,D)
    {
        float inv0 = 1.f / lrow[r0 + lq];
        float inv1 = 1.f / lrow[r0 + lq + 8];
        int t0 = q0 + r0 + lq;
#pragma unroll
        for (int nt = 0; nt < 8; nt++) {
            int c = oc0 + nt * 8 + lr * 2;
            float* y0 = Y + ((((size_t)b * TT + t0) * HQ + h) * DD + c);
            float* y1 = Y + ((((size_t)b * TT + t0 + 8) * HQ + h) * DD + c);
            *(float2*)y0 = make_float2(oacc[nt][0] * inv0, oacc[nt][1] * inv0);
            *(float2*)y1 = make_float2(oacc[nt][2] * inv1, oacc[nt][3] * inv1);
        }
    }
}

// ---------------- launch ----------------
extern "C" void kernel_launch(void* const* d_in, const int* in_sizes, int n_in,
                              void* d_out, int out_size)
{
    const float* query = (const float*)d_in[0];
    const float* key   = (const float*)d_in[1];
    const float* value = (const float*)d_in[2];
    const float* freqs = (const float*)d_in[3];
    const float* Wq = (const float*)d_in[5];
    const float* bq = (const float*)d_in[6];
    const float* Wk = (const float*)d_in[7];
    const float* bk = (const float*)d_in[8];
    const float* Wv = (const float*)d_in[9];
    const float* bv = (const float*)d_in[10];
    const float* Wo = (const float*)d_in[11];
    const float* bo = (const float*)d_in[12];
    float* out = (float*)d_out;

    float *Qb, *Kb, *Vb, *Yb;
    cudaGetSymbolAddress((void**)&Qb, g_Q);
    cudaGetSymbolAddress((void**)&Kb, g_K);
    cudaGetSymbolAddress((void**)&Vb, g_V);
    cudaGetSymbolAddress((void**)&Yb, g_Y);

    cudaFuncSetAttribute(gemm_mma_kernel,
                         cudaFuncAttributeMaxDynamicSharedMemorySize, GEMM_SMEM_BYTES);
    cudaFuncSetAttribute(flash_attn_kernel,
                         cudaFuncAttributeMaxDynamicSharedMemorySize, FLASH_SMEM_BYTES);

    dim3 blk(256);
    gemm_mma_kernel<<<dim3(EE / BN, MM / BM), blk, GEMM_SMEM_BYTES>>>(query, Wq, bq, Qb, MM, EE, EE);
    gemm_mma_kernel<<<dim3(KVE / BN, MM / BM), blk, GEMM_SMEM_BYTES>>>(key,   Wk, bk, Kb, MM, KVE, EE);
    gemm_mma_kernel<<<dim3(KVE / BN, MM / BM), blk, GEMM_SMEM_BYTES>>>(value, Wv, bv, Vb, MM, KVE, EE);

    {
        int totq = BZ * TT * HQ * (DD / 2);
        rope_kernel<<<(totq + 255) / 256, 256>>>(Qb, freqs, HQ);
        int totk = BZ * TT * HKV * (DD / 2);
        rope_kernel<<<(totk + 255) / 256, 256>>>(Kb, freqs, HKV);
    }

    flash_attn_kernel<<<dim3(TT / BQ, HQ, BZ), 256, FLASH_SMEM_BYTES>>>(Qb, Kb, Vb, Yb);

    gemm_mma_kernel<<<dim3(EE / BN, MM / BM), blk, GEMM_SMEM_BYTES>>>(Yb, Wo, bo, out, MM, EE, EE);
}